// round 8
// baseline (speedup 1.0000x reference)
#include <cuda_runtime.h>
#include <cuda_bf16.h>
#include <cstdint>
#include <math.h>

// 3 stacked dilated LSTM layers (rates 1,2,4), T=512, B=128, H=D=256, fp32 I/O.
// presplit(X,W) -> gemm gx = X@Wih^T + b -> recurrent scan with warp-local
// steps: 128 thr/CTA, 4 warps; each warp owns 4 h-cols x all gates x full K,
// A-frags resident in registers, pointwise fused via shfl_xor(16).

#define Hc    256
#define BATCH 128
#define TT    512
#define URS2  264            // u row stride (bf16 elems)
#define GXS   72             // gemm smem k-stride (shorts)

__device__ float          g_gx[(size_t)TT * BATCH * 1024];   // 256 MB
__device__ unsigned       g_hx[2][512 * 256];                // h: u32 = hi | lo<<16
__device__ unsigned short g_xh[(size_t)TT * BATCH * 256];
__device__ unsigned short g_xl[(size_t)TT * BATCH * 256];
__device__ unsigned short g_wh[1024 * 256];
__device__ unsigned short g_wl[1024 * 256];
__device__ unsigned       g_flag[8][16 * 32];                // 128B-apart flags

__device__ __forceinline__ void flag_set(unsigned* p, unsigned v) {
    asm volatile("st.release.gpu.global.u32 [%0], %1;" :: "l"(p), "r"(v) : "memory");
}
__device__ __forceinline__ unsigned flag_get(unsigned* p) {
    unsigned v;
    asm volatile("ld.acquire.gpu.global.u32 %0, [%1];" : "=r"(v) : "l"(p) : "memory");
    return v;
}
__device__ __forceinline__ unsigned prmt_(unsigned a, unsigned b, unsigned s) {
    unsigned d;
    asm("prmt.b32 %0, %1, %2, %3;" : "=r"(d) : "r"(a), "r"(b), "r"(s));
    return d;
}
__device__ __forceinline__ float sigmoidf_(float x) {
    return 1.0f / (1.0f + expf(-x));
}
__device__ __forceinline__ void split_pack(float x, float y,
                                           unsigned& hi, unsigned& lo) {
    __nv_bfloat162 h2, l2;
    h2.x = __float2bfloat16(x);
    h2.y = __float2bfloat16(y);
    l2.x = __float2bfloat16(x - __bfloat162float(h2.x));
    l2.y = __float2bfloat16(y - __bfloat162float(h2.y));
    hi = *(unsigned*)&h2;
    lo = *(unsigned*)&l2;
}
__device__ __forceinline__ void mma16816(float d[4], const unsigned a[4],
                                         unsigned b0, unsigned b1) {
    asm volatile(
        "mma.sync.aligned.m16n8k16.row.col.f32.bf16.bf16.f32 "
        "{%0,%1,%2,%3},{%4,%5,%6,%7},{%8,%9},{%0,%1,%2,%3};"
        : "+f"(d[0]), "+f"(d[1]), "+f"(d[2]), "+f"(d[3])
        : "r"(a[0]), "r"(a[1]), "r"(a[2]), "r"(a[3]), "r"(b0), "r"(b1));
}

// ============================================================================
// presplit: fp32 -> bf16 hi/lo planes
// ============================================================================
extern "C" __global__ void __launch_bounds__(512, 2)
presplit(const float* __restrict__ src, unsigned* __restrict__ dh,
         unsigned* __restrict__ dl, int n2)
{
    int i = blockIdx.x * 512 + threadIdx.x;
    if (i < n2) {
        float2 v = ((const float2*)src)[i];
        unsigned h, l;
        split_pack(v.x, v.y, h, l);
        dh[i] = h;
        dl[i] = l;
    }
}

// ============================================================================
// gemm: g_gx[row, R] = sum_k X[row,k]*W[R,k] + b1[R] + b2[R]   (pre-split bf16)
// grid (8, 512)
// ============================================================================
extern "C" __global__ void __launch_bounds__(512, 1)
gemm_gx(const float* __restrict__ b1, const float* __restrict__ b2)
{
    extern __shared__ char sm[];
    unsigned short* Xh = (unsigned short*)sm;        // 128 x GXS
    unsigned short* Xl = Xh + 128 * GXS;
    unsigned short* Wh = Xl + 128 * GXS;
    unsigned short* Wl = Wh + 128 * GXS;
    float* bias_s = (float*)(Wl + 128 * GXS);

    const int bn = blockIdx.x, bm = blockIdx.y;
    const int tid  = threadIdx.x;
    const int wid  = tid >> 5, lane = tid & 31;
    const int wm   = wid >> 2, wn = wid & 3;
    const int gid  = lane >> 2, t4 = lane & 3;

    if (tid < 128) bias_s[tid] = b1[bn * 128 + tid] + b2[bn * 128 + tid];

    float dd[2][4][4];
    #pragma unroll
    for (int mt = 0; mt < 2; ++mt)
        #pragma unroll
        for (int nt = 0; nt < 4; ++nt)
            #pragma unroll
            for (int r = 0; r < 4; ++r) dd[mt][nt][r] = 0.f;

    const int r_ld = tid >> 2;
    const int p_ld = tid & 3;
    const size_t xoff = (size_t)(bm * 128 + r_ld) * 256;
    const size_t woff = (size_t)(bn * 128 + r_ld) * 256;

    for (int kp = 0; kp < 4; ++kp) {
        __syncthreads();
        int kg = kp * 64 + p_ld * 16;
        int kl = p_ld * 16;
        *(uint4*)(Xh + r_ld * GXS + kl)     = *(const uint4*)(g_xh + xoff + kg);
        *(uint4*)(Xh + r_ld * GXS + kl + 8) = *(const uint4*)(g_xh + xoff + kg + 8);
        *(uint4*)(Xl + r_ld * GXS + kl)     = *(const uint4*)(g_xl + xoff + kg);
        *(uint4*)(Xl + r_ld * GXS + kl + 8) = *(const uint4*)(g_xl + xoff + kg + 8);
        *(uint4*)(Wh + r_ld * GXS + kl)     = *(const uint4*)(g_wh + woff + kg);
        *(uint4*)(Wh + r_ld * GXS + kl + 8) = *(const uint4*)(g_wh + woff + kg + 8);
        *(uint4*)(Wl + r_ld * GXS + kl)     = *(const uint4*)(g_wl + woff + kg);
        *(uint4*)(Wl + r_ld * GXS + kl + 8) = *(const uint4*)(g_wl + woff + kg + 8);
        __syncthreads();

        #pragma unroll
        for (int i = 0; i < 4; ++i) {
            int k0 = i * 16 + t4 * 2;
            unsigned ah[2][4], al[2][4];
            #pragma unroll
            for (int mt = 0; mt < 2; ++mt) {
                int r0 = wm * 32 + mt * 16;
                ah[mt][0] = *(unsigned*)(Xh + (r0 + gid)     * GXS + k0);
                ah[mt][1] = *(unsigned*)(Xh + (r0 + gid + 8) * GXS + k0);
                ah[mt][2] = *(unsigned*)(Xh + (r0 + gid)     * GXS + k0 + 8);
                ah[mt][3] = *(unsigned*)(Xh + (r0 + gid + 8) * GXS + k0 + 8);
                al[mt][0] = *(unsigned*)(Xl + (r0 + gid)     * GXS + k0);
                al[mt][1] = *(unsigned*)(Xl + (r0 + gid + 8) * GXS + k0);
                al[mt][2] = *(unsigned*)(Xl + (r0 + gid)     * GXS + k0 + 8);
                al[mt][3] = *(unsigned*)(Xl + (r0 + gid + 8) * GXS + k0 + 8);
            }
            #pragma unroll
            for (int nt = 0; nt < 4; ++nt) {
                int n0 = wn * 32 + nt * 8;
                unsigned bh0 = *(unsigned*)(Wh + (n0 + gid) * GXS + k0);
                unsigned bh1 = *(unsigned*)(Wh + (n0 + gid) * GXS + k0 + 8);
                unsigned bl0 = *(unsigned*)(Wl + (n0 + gid) * GXS + k0);
                unsigned bl1 = *(unsigned*)(Wl + (n0 + gid) * GXS + k0 + 8);
                #pragma unroll
                for (int mt = 0; mt < 2; ++mt) {
                    mma16816(dd[mt][nt], ah[mt], bh0, bh1);
                    mma16816(dd[mt][nt], ah[mt], bl0, bl1);
                    mma16816(dd[mt][nt], al[mt], bh0, bh1);
                }
            }
        }
    }

    #pragma unroll
    for (int mt = 0; mt < 2; ++mt)
        #pragma unroll
        for (int nt = 0; nt < 4; ++nt) {
            int rowA = bm * 128 + wm * 32 + mt * 16 + gid;
            int cl   = wn * 32 + nt * 8 + 2 * t4;
            int col  = bn * 128 + cl;
            float bx = bias_s[cl], by = bias_s[cl + 1];
            *(float2*)(g_gx + (size_t)rowA * 1024 + col) =
                make_float2(dd[mt][nt][0] + bx, dd[mt][nt][1] + by);
            *(float2*)(g_gx + (size_t)(rowA + 8) * 1024 + col) =
                make_float2(dd[mt][nt][2] + bx, dd[mt][nt][3] + by);
        }
}

// ============================================================================
// recur: grid (16 gate-CTAs, 8 batch-blocks), 128 threads. NT16 = Nper/16.
// Warp qd owns h-cols g*16 + qd*4 .. +3, all 4 gates, full K=256.
// ============================================================================
template<int NT16>
__global__ void __launch_bounds__(128, 1)
recur(const float* __restrict__ WhhL, float* __restrict__ out,
      int layer, int rate, int Td, unsigned stepBase)
{
    constexpr int Nper = NT16 * 16;

    extern __shared__ unsigned short sm2[];
    unsigned short* u_hi = sm2;                       // (16*NT16) x URS2
    unsigned short* u_lo = u_hi + 16 * NT16 * URS2;

    const int g   = blockIdx.x;
    const int nb  = blockIdx.y;
    const int tid = threadIdx.x;
    const int qd  = tid >> 5;         // warp id = col-quad
    const int lane = tid & 31;
    const int gid = lane >> 2, t4 = lane & 3;
    const int ga  = gid >> 2;         // 0/1: gate parity of row gid
    const int e   = gid & 3;          // local col within quad
    const int nG0 = nb * Nper;
    const int jcol = g * 16 + qd * 4 + e;   // this thread's h-column

    // ---- stationary A fragments: warp rows m = gate*4 + ecol
    // row gid   -> gate ga,   col e ;  row gid+8 -> gate ga+2, col e
    unsigned a_hi[16][4], a_lo[16][4];
    {
        const int rowA = ga * 256 + jcol;         // W row for frag rows gid
        const int rowB = (ga + 2) * 256 + jcol;   // W row for frag rows gid+8
        #pragma unroll
        for (int i = 0; i < 16; ++i) {
            int k = i * 16 + t4 * 2;
            float2 vA0 = *(const float2*)(WhhL + (size_t)rowA * 256 + k);
            float2 vB0 = *(const float2*)(WhhL + (size_t)rowB * 256 + k);
            float2 vA1 = *(const float2*)(WhhL + (size_t)rowA * 256 + k + 8);
            float2 vB1 = *(const float2*)(WhhL + (size_t)rowB * 256 + k + 8);
            split_pack(vA0.x, vA0.y, a_hi[i][0], a_lo[i][0]);
            split_pack(vB0.x, vB0.y, a_hi[i][1], a_lo[i][1]);
            split_pack(vA1.x, vA1.y, a_hi[i][2], a_lo[i][2]);
            split_pack(vB1.x, vB1.y, a_hi[i][3], a_lo[i][3]);
        }
    }

    unsigned* flags = &g_flag[nb][0];

    float gxp[NT16][2][4], creg[NT16][2], hsv[NT16][2];
    #pragma unroll
    for (int nt = 0; nt < NT16; ++nt) { creg[nt][0] = 0.f; creg[nt][1] = 0.f; }

    // gx prefetch for step 0; thread's batch cols: 2*t4 + ga + 8*p
    #pragma unroll
    for (int nt = 0; nt < NT16; ++nt)
        #pragma unroll
        for (int p = 0; p < 2; ++p) {
            int col = 2 * t4 + ga + 8 * p;
            int nG  = nG0 + nt * 16 + col;
            int rr = nG >> 7, bat = nG & 127;
            const float* gp = g_gx + ((size_t)(rr * BATCH + bat)) * 1024 + jcol;
            #pragma unroll
            for (int qq = 0; qq < 4; ++qq) gxp[nt][p][qq] = gp[qq * 256];
        }

    for (int s = 0; s < Td; ++s) {
        float d[NT16][8];
        #pragma unroll
        for (int nt = 0; nt < NT16; ++nt)
            #pragma unroll
            for (int r = 0; r < 8; ++r) d[nt][r] = 0.f;

        if (s > 0) {
            // wait for all 16 gate-CTAs to finish step s-1
            if (qd == 0 && lane < 16) {
                unsigned target = stepBase + (unsigned)s;
                while (flag_get(&flags[lane * 32]) < target) { }
            }
            __syncthreads();

            // ---- stage h (interleaved u32) -> smem hi/lo planes
            {
                const unsigned* hb = g_hx[(s + 1) & 1] + (size_t)nG0 * 256;
                #pragma unroll
                for (int it = 0; it < NT16 * 8; ++it) {
                    int idx = tid + 128 * it;        // uint4 index
                    int n  = idx >> 6;
                    int k0 = (idx & 63) * 4;
                    uint4 v = *(const uint4*)(hb + n * 256 + k0);
                    unsigned hiA = prmt_(v.x, v.y, 0x5410), loA = prmt_(v.x, v.y, 0x7632);
                    unsigned hiB = prmt_(v.z, v.w, 0x5410), loB = prmt_(v.z, v.w, 0x7632);
                    *(uint2*)(u_hi + n * URS2 + k0) = make_uint2(hiA, hiB);
                    *(uint2*)(u_lo + n * URS2 + k0) = make_uint2(loA, loB);
                }
            }
            __syncthreads();

            // ---- warp-local HMMA: 16 rows (4 gates x 4 cols) x 16 batch x K=256
            #pragma unroll
            for (int i = 0; i < 16; ++i) {
                int kof = i * 16 + t4 * 2;
                #pragma unroll
                for (int nt = 0; nt < NT16; ++nt) {
                    const unsigned short* uh = u_hi + (nt * 16 + gid) * URS2 + kof;
                    const unsigned short* ul = u_lo + (nt * 16 + gid) * URS2 + kof;
                    unsigned bh0a = *(const unsigned*)uh;
                    unsigned bh0b = *(const unsigned*)(uh + 8);
                    unsigned bl0a = *(const unsigned*)ul;
                    unsigned bl0b = *(const unsigned*)(ul + 8);
                    unsigned bh8a = *(const unsigned*)(uh + 8 * URS2);
                    unsigned bh8b = *(const unsigned*)(uh + 8 * URS2 + 8);
                    unsigned bl8a = *(const unsigned*)(ul + 8 * URS2);
                    unsigned bl8b = *(const unsigned*)(ul + 8 * URS2 + 8);
                    mma16816(d[nt] + 0, a_hi[i], bh0a, bh0b);
                    mma16816(d[nt] + 0, a_hi[i], bl0a, bl0b);
                    mma16816(d[nt] + 0, a_lo[i], bh0a, bh0b);
                    mma16816(d[nt] + 4, a_hi[i], bh8a, bh8b);
                    mma16816(d[nt] + 4, a_hi[i], bl8a, bl8b);
                    mma16816(d[nt] + 4, a_lo[i], bh8a, bh8b);
                }
            }
        }

        // ---- warp-local pointwise: exchange other-parity gates via shfl_xor(16)
        {
            unsigned* dh = g_hx[s & 1];
            #pragma unroll
            for (int nt = 0; nt < NT16; ++nt) {
                float r[8];
                #pragma unroll
                for (int j = 0; j < 8; ++j)
                    r[j] = __shfl_xor_sync(0xffffffffu, d[nt][j], 16);
                #pragma unroll
                for (int p = 0; p < 2; ++p) {
                    float iv, fv, gv_, ov;
                    if (ga == 0) {
                        iv = d[nt][4 * p + 0]; gv_ = d[nt][4 * p + 2];
                        fv = r[4 * p + 0];     ov  = r[4 * p + 2];
                    } else {
                        iv = r[4 * p + 1];     gv_ = r[4 * p + 3];
                        fv = d[nt][4 * p + 1]; ov  = d[nt][4 * p + 3];
                    }
                    float ig = sigmoidf_(gxp[nt][p][0] + iv);
                    float fg = sigmoidf_(gxp[nt][p][1] + fv);
                    float gt = tanhf(gxp[nt][p][2] + gv_);
                    float og = sigmoidf_(gxp[nt][p][3] + ov);
                    float cnew = fg * creg[nt][p] + ig * gt;
                    float hnew = og * tanhf(cnew);
                    creg[nt][p] = cnew;
                    hsv[nt][p]  = hnew;

                    int col = 2 * t4 + ga + 8 * p;
                    int nG  = nG0 + nt * 16 + col;
                    __nv_bfloat16 hh = __float2bfloat16(hnew);
                    __nv_bfloat16 hl = __float2bfloat16(hnew - __bfloat162float(hh));
                    unsigned hv = (unsigned)*(unsigned short*)&hh
                                | ((unsigned)*(unsigned short*)&hl << 16);
                    dh[(size_t)nG * 256 + jcol] = hv;
                }
            }
        }
        __syncthreads();
        if (tid == 0) flag_set(&flags[g * 32], stepBase + (unsigned)(s + 1));

        // ---- shadowed behind barrier: out stores + next-step gx prefetch
        #pragma unroll
        for (int nt = 0; nt < NT16; ++nt)
            #pragma unroll
            for (int p = 0; p < 2; ++p) {
                int col = 2 * t4 + ga + 8 * p;
                int nG  = nG0 + nt * 16 + col;
                int rr = nG >> 7, bat = nG & 127;
                int time = s * rate + rr;
                out[((size_t)(layer * TT + time) * BATCH + bat) * Hc + jcol] = hsv[nt][p];
                if (s + 1 < Td) {
                    int time2 = (s + 1) * rate + rr;
                    const float* gp = g_gx + ((size_t)(time2 * BATCH + bat)) * 1024 + jcol;
                    #pragma unroll
                    for (int qq = 0; qq < 4; ++qq) gxp[nt][p][qq] = gp[qq * 256];
                }
            }
    }
}

extern "C" void kernel_launch(void* const* d_in, const int* in_sizes, int n_in,
                              void* d_out, int out_size)
{
    const float* x   = (const float*)d_in[0];
    const float* Wih = (const float*)d_in[1];
    const float* Whh = (const float*)d_in[2];
    const float* bih = (const float*)d_in[3];
    const float* bhh = (const float*)d_in[4];
    float* out = (float*)d_out;

    const int gsm = 4 * 128 * GXS * 2 + 512;
    const int rsm1 = 16 * 1 * URS2 * 2 * 2;
    const int rsm2 = 16 * 2 * URS2 * 2 * 2;
    const int rsm4 = 16 * 4 * URS2 * 2 * 2;
    cudaFuncSetAttribute(gemm_gx, cudaFuncAttributeMaxDynamicSharedMemorySize, gsm);
    cudaFuncSetAttribute(recur<1>, cudaFuncAttributeMaxDynamicSharedMemorySize, rsm1);
    cudaFuncSetAttribute(recur<2>, cudaFuncAttributeMaxDynamicSharedMemorySize, rsm2);
    cudaFuncSetAttribute(recur<4>, cudaFuncAttributeMaxDynamicSharedMemorySize, rsm4);

    void *flagp, *xh, *xl, *wh, *wl;
    cudaGetSymbolAddress(&flagp, g_flag);
    cudaGetSymbolAddress(&xh, g_xh);
    cudaGetSymbolAddress(&xl, g_xl);
    cudaGetSymbolAddress(&wh, g_wh);
    cudaGetSymbolAddress(&wl, g_wl);
    cudaMemsetAsync(flagp, 0, 8 * 16 * 32 * sizeof(unsigned), 0);

    const size_t le = (size_t)TT * BATCH * Hc;
    const int n2x = (int)(le / 2);
    const int n2w = 1024 * 256 / 2;
    dim3 ggrid(8, 512), rgrid(16, 8);

    // layer 0
    presplit<<<n2x / 512, 512>>>(x, (unsigned*)xh, (unsigned*)xl, n2x);
    presplit<<<n2w / 512, 512>>>(Wih, (unsigned*)wh, (unsigned*)wl, n2w);
    gemm_gx<<<ggrid, 512, gsm>>>(bih, bhh);
    recur<1><<<rgrid, 128, rsm1>>>(Whh, out, 0, 1, 512, 0u);
    // layer 1
    presplit<<<n2x / 512, 512>>>(out, (unsigned*)xh, (unsigned*)xl, n2x);
    presplit<<<n2w / 512, 512>>>(Wih + 1024 * 256, (unsigned*)wh, (unsigned*)wl, n2w);
    gemm_gx<<<ggrid, 512, gsm>>>(bih + 1024, bhh + 1024);
    recur<2><<<rgrid, 128, rsm2>>>(Whh + 1024 * 256, out, 1, 2, 256, 512u);
    // layer 2
    presplit<<<n2x / 512, 512>>>(out + le, (unsigned*)xh, (unsigned*)xl, n2x);
    presplit<<<n2w / 512, 512>>>(Wih + 2 * 1024 * 256, (unsigned*)wh, (unsigned*)wl, n2w);
    gemm_gx<<<ggrid, 512, gsm>>>(bih + 2048, bhh + 2048);
    recur<4><<<rgrid, 128, rsm4>>>(Whh + 2 * 1024 * 256, out, 2, 4, 128, 768u);
}